// round 14
// baseline (speedup 1.0000x reference)
#include <cuda_runtime.h>
#include <cuda_bf16.h>

// Problem constants: N=150000 nodes, E=1e6 edges, D=64, 3 layers.
#define NMAX   150016
#define EMAX   1000448
#define DIM    64
#define SOFTEPS 1e-16f
#define NEGINF __int_as_float(0xff800000)

// Scratch (no allocations allowed -> __device__ globals).
__device__ float g_Z[NMAX * DIM];
__device__ float g_bufA[NMAX * DIM];
__device__ float g_bufB[NMAX * DIM];
// src-CSR only (score+softmax+scatter all group by src)
__device__ int   g_cntS[NMAX], g_rsS[NMAX + 1], g_curS[NMAX];
__device__ int   g_dstS[EMAX];     // dst node at src-CSR slot
__device__ float g_eterm[EMAX];    // 64*exp(scale*ea[e]) at src-CSR slot
__device__ int   g_bsumS[1024];

__device__ __forceinline__ const float* sel_cur(int sel, const float* emb_in) {
    if (sel == 0) return emb_in;
    return (sel == 1) ? g_bufA : g_bufB;
}

// ---------------- CSR build (once per launch; src side only) ----------------
__global__ void k_cnt_zero(int N) {
    int i = blockIdx.x * blockDim.x + threadIdx.x;
    if (i < N) g_cntS[i] = 0;
}
__global__ void k_hist(const int* __restrict__ ei, int E) {
    int e = blockIdx.x * blockDim.x + threadIdx.x;
    if (e < E) atomicAdd(&g_cntS[ei[e]], 1);
}
__global__ void k_scan1(int N) {
    __shared__ int sh[256];
    int i = blockIdx.x * 256 + threadIdx.x;
    int v = (i < N) ? g_cntS[i] : 0;
    sh[threadIdx.x] = v;
    __syncthreads();
    for (int o = 1; o < 256; o <<= 1) {
        int t = (threadIdx.x >= o) ? sh[threadIdx.x - o] : 0;
        __syncthreads();
        sh[threadIdx.x] += t;
        __syncthreads();
    }
    if (i < N) g_rsS[i] = sh[threadIdx.x] - v;
    if (threadIdx.x == 255) g_bsumS[blockIdx.x] = sh[255];
}
__global__ void k_scan2(int nb) {
    __shared__ int sh[1024];
    int t = threadIdx.x;
    int v = (t < nb) ? g_bsumS[t] : 0;
    sh[t] = v;
    __syncthreads();
    for (int o = 1; o < 1024; o <<= 1) {
        int u = (t >= o) ? sh[t - o] : 0;
        __syncthreads();
        sh[t] += u;
        __syncthreads();
    }
    if (t < nb) g_bsumS[t] = sh[t] - v;
}
__global__ void k_scan3(int N, int E) {
    int i = blockIdx.x * blockDim.x + threadIdx.x;
    if (i < N) {
        int r = g_rsS[i] + g_bsumS[i >> 8];
        g_rsS[i] = r;
        g_curS[i] = r;
    }
    if (i == 0) g_rsS[N] = E;
}
__global__ void k_build_scatter(const int* __restrict__ ei, const float* __restrict__ ea,
                                const float* __restrict__ scale_p, int E) {
    int e = blockIdx.x * blockDim.x + threadIdx.x;
    if (e >= E) return;
    int src = ei[e], dst = ei[E + e];
    int ps = atomicAdd(&g_curS[src], 1);
    g_dstS[ps]  = dst;
    g_eterm[ps] = 64.0f * __expf(scale_p[0] * ea[e]);
}

// ---------------- per-layer kernels ----------------
// Z = cur @ W (32 rows/block, 8 outputs/thread). Also prepares the scatter
// target for its 32 rows: zeroes next (l<2) or prefills out=(emb+A+B)/4 (l==2).
__global__ void k_gemm64(int curSel, const float* __restrict__ emb_in,
                         const float* __restrict__ W, float* __restrict__ out,
                         int N, int layer) {
    __shared__ float sW[DIM * DIM];
    __shared__ float sX[32 * 65];
    const float* X = sel_cur(curSel, emb_in);
    int tid = threadIdx.x;
    #pragma unroll
    for (int i = tid; i < DIM * DIM; i += 256) sW[i] = W[i];
    int rowBase = blockIdx.x * 32;
    #pragma unroll
    for (int i = tid; i < 32 * DIM; i += 256) {
        int r = i >> 6, c = i & 63;
        int row = rowBase + r;
        sX[r * 65 + c] = (row < N) ? X[(size_t)row * DIM + c] : 0.0f;
    }
    // Prepare scatter target for this block's rows (32*16 float4 slots).
    if (layer < 2) {
        float* nxt = (layer == 0) ? g_bufA : g_bufB;
        for (int i = tid; i < 32 * 16; i += 256) {
            int row = rowBase + (i >> 4);
            if (row < N)
                ((float4*)(nxt + (size_t)row * DIM))[i & 15] =
                    make_float4(0.f, 0.f, 0.f, 0.f);
        }
    } else {
        for (int i = tid; i < 32 * 16; i += 256) {
            int row = rowBase + (i >> 4);
            if (row < N) {
                size_t off = (size_t)row * DIM;
                float4 e0 = ((const float4*)(emb_in + off))[i & 15];
                float4 a  = ((const float4*)(g_bufA + off))[i & 15];
                float4 b  = ((const float4*)(g_bufB + off))[i & 15];
                ((float4*)(out + off))[i & 15] = make_float4(
                    (e0.x + a.x + b.x) * 0.25f, (e0.y + a.y + b.y) * 0.25f,
                    (e0.z + a.z + b.z) * 0.25f, (e0.w + a.w + b.w) * 0.25f);
            }
        }
    }
    __syncthreads();
    int r  = tid >> 3;
    int cg = (tid & 7) * 8;
    float a0=0,a1=0,a2=0,a3=0,a4=0,a5=0,a6=0,a7=0;
    #pragma unroll
    for (int k = 0; k < DIM; k++) {
        float xv = sX[r * 65 + k];
        float4 w0 = *(const float4*)&sW[k * DIM + cg];
        float4 w1 = *(const float4*)&sW[k * DIM + cg + 4];
        a0 = fmaf(xv, w0.x, a0); a1 = fmaf(xv, w0.y, a1);
        a2 = fmaf(xv, w0.z, a2); a3 = fmaf(xv, w0.w, a3);
        a4 = fmaf(xv, w1.x, a4); a5 = fmaf(xv, w1.y, a5);
        a6 = fmaf(xv, w1.z, a6); a7 = fmaf(xv, w1.w, a7);
    }
    int row = rowBase + r;
    if (row < N) {
        float4* o = (float4*)&g_Z[(size_t)row * DIM + cg];
        o[0] = make_float4(a0, a1, a2, a3);
        o[1] = make_float4(a4, a5, a6, a7);
    }
}

// Fused score + segment-softmax + scatter-aggregate: one warp per src node.
// deg<=32 hot path: LANE-PARALLEL score — lane t computes the FULL dot for
// edge t alone (x row broadcast from smem, 16 independent Z loads, no
// shuffles). Softmax operates directly on per-lane s. Scatter is the proven
// r9 loop (no shuffles -> divergent halves safe).
// out_t==nullptr -> target is g_bufA (layer 0) / g_bufB (layer 1).
__global__ void k_fused(int curSel, const float* __restrict__ emb_in,
                        const float* __restrict__ bias_p,
                        float* out_t, float cscale, int N, int layer) {
    __shared__ float  ssc[8][32];           // alpha staging, 8 warps/block
    __shared__ float4 xbuf[8][16];          // x row per warp (64 floats)
    int gt   = blockIdx.x * blockDim.x + threadIdx.x;
    int v    = gt >> 5;
    int lane = threadIdx.x & 31;
    int wid  = threadIdx.x >> 5;
    if (v >= N) return;
    int beg = g_rsS[v], end = g_rsS[v + 1];
    int deg = end - beg;
    if (deg == 0) return;
    float* target = out_t ? out_t : ((layer == 0) ? g_bufA : g_bufB);
    const float* cur = sel_cur(curSel, emb_in);
    int half = lane >> 4;
    int hl   = lane & 15;
    float bias = bias_p[layer];

    if (deg <= 32) {
        // stage x row into smem (lanes 0..15, one float4 each)
        if (lane < 16)
            xbuf[wid][lane] = ((const float4*)(cur + (size_t)v * DIM))[lane];
        __syncwarp();
        // lane-parallel score: edge index = lane (clamped; dedups to same line)
        int j = beg + min(lane, deg - 1);
        int dstL  = g_dstS[j];
        float et  = g_eterm[j];
        const float4* zr = (const float4*)(g_Z + (size_t)dstL * DIM);
        float p0 = 0.f, p1 = 0.f, p2 = 0.f, p3 = 0.f;
        #pragma unroll
        for (int k = 0; k < 16; k += 4) {
            float4 za = zr[k],     xa = xbuf[wid][k];
            float4 zb = zr[k + 1], xb = xbuf[wid][k + 1];
            float4 zc = zr[k + 2], xc = xbuf[wid][k + 2];
            float4 zd = zr[k + 3], xd = xbuf[wid][k + 3];
            p0 += za.x*xa.x + za.y*xa.y + za.z*xa.z + za.w*xa.w;
            p1 += zb.x*xb.x + zb.y*xb.y + zb.z*xb.z + zb.w*xb.w;
            p2 += zc.x*xc.x + zc.y*xc.y + zc.z*xc.z + zc.w*xc.w;
            p3 += zd.x*xd.x + zd.y*xd.y + zd.z*xd.z + zd.w*xd.w;
        }
        float s = (p0 + p1) + (p2 + p3) + et + bias;
        s = (s >= 0.0f) ? s : 0.2f * s;
        if (lane >= deg) s = NEGINF;
        // softmax over the warp's deg edges (per-lane s, no smem round-trip)
        float m = s;
        #pragma unroll
        for (int o = 16; o; o >>= 1)
            m = fmaxf(m, __shfl_xor_sync(0xffffffffu, m, o));
        float ex = (lane < deg) ? __expf(s - m) : 0.0f;
        float den = ex;
        #pragma unroll
        for (int o = 16; o; o >>= 1)
            den += __shfl_xor_sync(0xffffffffu, den, o);
        ssc[wid][lane] = ex / (den + SOFTEPS) * cscale;
        __syncwarp();
        // scatter (r9 form): 16-lane halves, float4 RED per edge
        float4 x = xbuf[wid][hl];
        for (int t2 = half; t2 < deg; t2 += 2) {
            float al = ssc[wid][t2];
            int dst = g_dstS[beg + t2];
            atomicAdd(((float4*)(target + (size_t)dst * DIM)) + hl,
                      make_float4(al * x.x, al * x.y, al * x.z, al * x.w));
        }
    } else {
        // Rare fallback (deg>32): 3 passes, recompute; scatter inline in pass 3.
        unsigned hmask = 0xFFFFu << (half << 4);
        float4 x = ((const float4*)(cur + (size_t)v * DIM))[hl];
        float mloc = NEGINF;
        for (int t2 = half; t2 < deg; t2 += 2) {
            int j = beg + t2;
            int dst = g_dstS[j];
            float4 z = ((const float4*)(g_Z + (size_t)dst * DIM))[hl];
            float p = z.x * x.x + z.y * x.y + z.z * x.z + z.w * x.w;
            #pragma unroll
            for (int o = 8; o; o >>= 1)
                p += __shfl_xor_sync(hmask, p, o, 16);
            float s = p + g_eterm[j] + bias;
            s = (s >= 0.0f) ? s : 0.2f * s;
            mloc = fmaxf(mloc, s);
        }
        #pragma unroll
        for (int o = 16; o; o >>= 1)
            mloc = fmaxf(mloc, __shfl_xor_sync(0xffffffffu, mloc, o));
        float dloc = 0.0f;
        for (int t2 = half; t2 < deg; t2 += 2) {
            int j = beg + t2;
            int dst = g_dstS[j];
            float4 z = ((const float4*)(g_Z + (size_t)dst * DIM))[hl];
            float p = z.x * x.x + z.y * x.y + z.z * x.z + z.w * x.w;
            #pragma unroll
            for (int o = 8; o; o >>= 1)
                p += __shfl_xor_sync(hmask, p, o, 16);
            float s = p + g_eterm[j] + bias;
            s = (s >= 0.0f) ? s : 0.2f * s;
            dloc += __expf(s - mloc);
        }
        #pragma unroll
        for (int o = 16; o; o >>= 1)
            dloc += __shfl_xor_sync(0xffffffffu, dloc, o);
        float den = dloc * 0.0625f;         // /16 (each edge counted by 16 lanes)
        float inv = cscale / (den + SOFTEPS);
        for (int t2 = half; t2 < deg; t2 += 2) {
            int j = beg + t2;
            int dst = g_dstS[j];
            float4 z = ((const float4*)(g_Z + (size_t)dst * DIM))[hl];
            float p = z.x * x.x + z.y * x.y + z.z * x.z + z.w * x.w;
            #pragma unroll
            for (int o = 8; o; o >>= 1)
                p += __shfl_xor_sync(hmask, p, o, 16);
            float s = p + g_eterm[j] + bias;
            s = (s >= 0.0f) ? s : 0.2f * s;
            float al = __expf(s - mloc) * inv;  // uniform across the half
            atomicAdd(((float4*)(target + (size_t)dst * DIM)) + hl,
                      make_float4(al * x.x, al * x.y, al * x.z, al * x.w));
        }
    }
}

extern "C" void kernel_launch(void* const* d_in, const int* in_sizes, int n_in,
                              void* d_out, int out_size) {
    const int*   ei    = (const int*)d_in[0];
    const float* ea    = (const float*)d_in[1];
    const float* emb   = (const float*)d_in[2];
    const float* W     = (const float*)d_in[3];
    const float* bias  = (const float*)d_in[4];
    const float* scale = (const float*)d_in[5];

    int E  = in_sizes[1];
    int ND = in_sizes[2];
    int N  = ND / DIM;

    const int T = 256;
    int blk_n   = (N + T - 1) / T;
    int blk_e   = (E + T - 1) / T;
    int blk_n32 = (N * 32 + T - 1) / T;       // warp per node

    // ---- build src-CSR (edge_index constant per launch) ----
    k_cnt_zero<<<blk_n, T>>>(N);
    k_hist<<<blk_e, T>>>(ei, E);
    k_scan1<<<blk_n, 256>>>(N);
    k_scan2<<<1, 1024>>>(blk_n);
    k_scan3<<<blk_n, T>>>(N, E);
    k_build_scatter<<<blk_e, T>>>(ei, ea, scale, E);

    float* out = (float*)d_out;
    float* out2 = out;
    if (out_size >= 2 * ND) {
        cudaMemcpyAsync(out, emb, (size_t)ND * sizeof(float),
                        cudaMemcpyDeviceToDevice, 0);
        out2 = out + ND;
    }

    // Layer schedule: cur: emb -> A -> B; scatter target: A, B, out2.
    const int curSel[3] = {0, 1, 2};
    for (int l = 0; l < 3; l++) {
        k_gemm64<<<(N + 31) / 32, T>>>(curSel[l], emb,
                                       W + (size_t)l * DIM * DIM, out2, N, l);
        k_fused<<<blk_n32, T>>>(curSel[l], emb, bias,
                                (l == 2) ? out2 : nullptr,
                                (l == 2) ? 0.25f : 1.0f, N, l);
    }
}

// round 15
// speedup vs baseline: 1.2586x; 1.2586x over previous
#include <cuda_runtime.h>
#include <cuda_bf16.h>

// Problem constants: N=150000 nodes, E=1e6 edges, D=64, 3 layers.
#define NMAX   150016
#define EMAX   1000448
#define DIM    64
#define SOFTEPS 1e-16f
#define NEGINF __int_as_float(0xff800000)

// Scratch (no allocations allowed -> __device__ globals).
__device__ float g_Z[NMAX * DIM];
__device__ float g_bufA[NMAX * DIM];
__device__ float g_bufB[NMAX * DIM];
// src-CSR only (score+softmax+scatter all group by src)
__device__ int   g_cntS[NMAX], g_rsS[NMAX + 1], g_curS[NMAX];
__device__ int   g_dstS[EMAX];     // dst node at src-CSR slot
__device__ float g_eterm[EMAX];    // 64*exp(scale*ea[e]) at src-CSR slot
__device__ int   g_bsumS[1024];

__device__ __forceinline__ const float* sel_cur(int sel, const float* emb_in) {
    if (sel == 0) return emb_in;
    return (sel == 1) ? g_bufA : g_bufB;
}

// ---------------- CSR build (once per launch; src side only) ----------------
__global__ void k_hist(const int* __restrict__ ei, int E) {
    int e = blockIdx.x * blockDim.x + threadIdx.x;
    if (e < E) atomicAdd(&g_cntS[ei[e]], 1);
}
// Reads counts AND zeroes them for the next replay (g_cntS is .bss-zeroed at
// module load, so the first run is consistent too).
__global__ void k_scan1(int N) {
    __shared__ int sh[256];
    int i = blockIdx.x * 256 + threadIdx.x;
    int v = 0;
    if (i < N) { v = g_cntS[i]; g_cntS[i] = 0; }
    sh[threadIdx.x] = v;
    __syncthreads();
    for (int o = 1; o < 256; o <<= 1) {
        int t = (threadIdx.x >= o) ? sh[threadIdx.x - o] : 0;
        __syncthreads();
        sh[threadIdx.x] += t;
        __syncthreads();
    }
    if (i < N) g_rsS[i] = sh[threadIdx.x] - v;
    if (threadIdx.x == 255) g_bsumS[blockIdx.x] = sh[255];
}
__global__ void k_scan2(int nb) {
    __shared__ int sh[1024];
    int t = threadIdx.x;
    int v = (t < nb) ? g_bsumS[t] : 0;
    sh[t] = v;
    __syncthreads();
    for (int o = 1; o < 1024; o <<= 1) {
        int u = (t >= o) ? sh[t - o] : 0;
        __syncthreads();
        sh[t] += u;
        __syncthreads();
    }
    if (t < nb) g_bsumS[t] = sh[t] - v;
}
__global__ void k_scan3(int N, int E) {
    int i = blockIdx.x * blockDim.x + threadIdx.x;
    if (i < N) {
        int r = g_rsS[i] + g_bsumS[i >> 8];
        g_rsS[i] = r;
        g_curS[i] = r;
    }
    if (i == 0) g_rsS[N] = E;
}
__global__ void k_build_scatter(const int* __restrict__ ei, const float* __restrict__ ea,
                                const float* __restrict__ scale_p, int E) {
    int e = blockIdx.x * blockDim.x + threadIdx.x;
    if (e >= E) return;
    int src = ei[e], dst = ei[E + e];
    int ps = atomicAdd(&g_curS[src], 1);
    g_dstS[ps]  = dst;
    g_eterm[ps] = 64.0f * __expf(scale_p[0] * ea[e]);
}

// ---------------- per-layer kernels ----------------
// Z = cur @ W (32 rows/block, 8 outputs/thread). Also prepares the scatter
// target for its 32 rows: zeroes next (l<2) or prefills out=(emb+A+B)/4 (l==2).
// Layer 0 additionally mirrors emb into out_copy (the harness's first output),
// replacing a separate 38MB memcpy.
__global__ void k_gemm64(int curSel, const float* __restrict__ emb_in,
                         const float* __restrict__ W, float* __restrict__ out,
                         float* __restrict__ out_copy, int N, int layer) {
    __shared__ float sW[DIM * DIM];
    __shared__ float sX[32 * 65];
    const float* X = sel_cur(curSel, emb_in);
    int tid = threadIdx.x;
    #pragma unroll
    for (int i = tid; i < DIM * DIM; i += 256) sW[i] = W[i];
    int rowBase = blockIdx.x * 32;
    #pragma unroll
    for (int i = tid; i < 32 * DIM; i += 256) {
        int r = i >> 6, c = i & 63;
        int row = rowBase + r;
        float xv = (row < N) ? X[(size_t)row * DIM + c] : 0.0f;
        sX[r * 65 + c] = xv;
        if (layer == 0 && out_copy && row < N)
            out_copy[(size_t)row * DIM + c] = xv;   // X==emb on layer 0
    }
    // Prepare scatter target for this block's rows (32*16 float4 slots).
    if (layer < 2) {
        float* nxt = (layer == 0) ? g_bufA : g_bufB;
        for (int i = tid; i < 32 * 16; i += 256) {
            int row = rowBase + (i >> 4);
            if (row < N)
                ((float4*)(nxt + (size_t)row * DIM))[i & 15] =
                    make_float4(0.f, 0.f, 0.f, 0.f);
        }
    } else {
        for (int i = tid; i < 32 * 16; i += 256) {
            int row = rowBase + (i >> 4);
            if (row < N) {
                size_t off = (size_t)row * DIM;
                float4 e0 = ((const float4*)(emb_in + off))[i & 15];
                float4 a  = ((const float4*)(g_bufA + off))[i & 15];
                float4 b  = ((const float4*)(g_bufB + off))[i & 15];
                ((float4*)(out + off))[i & 15] = make_float4(
                    (e0.x + a.x + b.x) * 0.25f, (e0.y + a.y + b.y) * 0.25f,
                    (e0.z + a.z + b.z) * 0.25f, (e0.w + a.w + b.w) * 0.25f);
            }
        }
    }
    __syncthreads();
    int r  = tid >> 3;
    int cg = (tid & 7) * 8;
    float a0=0,a1=0,a2=0,a3=0,a4=0,a5=0,a6=0,a7=0;
    #pragma unroll
    for (int k = 0; k < DIM; k++) {
        float xv = sX[r * 65 + k];
        float4 w0 = *(const float4*)&sW[k * DIM + cg];
        float4 w1 = *(const float4*)&sW[k * DIM + cg + 4];
        a0 = fmaf(xv, w0.x, a0); a1 = fmaf(xv, w0.y, a1);
        a2 = fmaf(xv, w0.z, a2); a3 = fmaf(xv, w0.w, a3);
        a4 = fmaf(xv, w1.x, a4); a5 = fmaf(xv, w1.y, a5);
        a6 = fmaf(xv, w1.z, a6); a7 = fmaf(xv, w1.w, a7);
    }
    int row = rowBase + r;
    if (row < N) {
        float4* o = (float4*)&g_Z[(size_t)row * DIM + cg];
        o[0] = make_float4(a0, a1, a2, a3);
        o[1] = make_float4(a4, a5, a6, a7);
    }
}

// Fused score + segment-softmax + scatter-aggregate: one warp per src node.
// (Exact 794.7us configuration: coalesced 16-lane halves, 2 edges in flight,
// half-scoped shuffle masks in deg-dependent loops.)
// out_t==nullptr -> target is g_bufA (layer 0) / g_bufB (layer 1).
__global__ void k_fused(int curSel, const float* __restrict__ emb_in,
                        const float* __restrict__ bias_p,
                        float* out_t, float cscale, int N, int layer) {
    __shared__ float ssc[8][32];            // 8 warps/block
    int gt   = blockIdx.x * blockDim.x + threadIdx.x;
    int v    = gt >> 5;
    int lane = threadIdx.x & 31;
    int wid  = threadIdx.x >> 5;
    if (v >= N) return;
    int beg = g_rsS[v], end = g_rsS[v + 1];
    int deg = end - beg;
    if (deg == 0) return;
    float* target = out_t ? out_t : ((layer == 0) ? g_bufA : g_bufB);
    const float* cur = sel_cur(curSel, emb_in);
    int half = lane >> 4;
    int hl   = lane & 15;
    unsigned hmask = 0xFFFFu << (half << 4);
    float4 x = ((const float4*)(cur + (size_t)v * DIM))[hl];
    float bias = bias_p[layer];

    if (deg <= 32) {
        for (int t2 = half; t2 < deg; t2 += 2) {
            int j = beg + t2;
            int dst = g_dstS[j];
            float4 z = ((const float4*)(g_Z + (size_t)dst * DIM))[hl];
            float p = z.x * x.x + z.y * x.y + z.z * x.z + z.w * x.w;
            #pragma unroll
            for (int o = 8; o; o >>= 1)
                p += __shfl_xor_sync(hmask, p, o, 16);
            float s = p + g_eterm[j] + bias;
            s = (s >= 0.0f) ? s : 0.2f * s;
            if (hl == 0) ssc[wid][t2] = s;
        }
        __syncwarp();
        float sv = (lane < deg) ? ssc[wid][lane] : NEGINF;
        float m = sv;
        #pragma unroll
        for (int o = 16; o; o >>= 1)
            m = fmaxf(m, __shfl_xor_sync(0xffffffffu, m, o));
        float ex = (lane < deg) ? __expf(sv - m) : 0.0f;
        float den = ex;
        #pragma unroll
        for (int o = 16; o; o >>= 1)
            den += __shfl_xor_sync(0xffffffffu, den, o);
        if (lane < deg)
            ssc[wid][lane] = ex / (den + SOFTEPS) * cscale;
        __syncwarp();
        for (int t2 = half; t2 < deg; t2 += 2) {
            int j = beg + t2;
            float al = ssc[wid][t2];
            int dst = g_dstS[j];
            atomicAdd(((float4*)(target + (size_t)dst * DIM)) + hl,
                      make_float4(al * x.x, al * x.y, al * x.z, al * x.w));
        }
    } else {
        // Rare fallback (deg>32): 3 passes, recompute; scatter inline in pass 3.
        float mloc = NEGINF;
        for (int t2 = half; t2 < deg; t2 += 2) {
            int j = beg + t2;
            int dst = g_dstS[j];
            float4 z = ((const float4*)(g_Z + (size_t)dst * DIM))[hl];
            float p = z.x * x.x + z.y * x.y + z.z * x.z + z.w * x.w;
            #pragma unroll
            for (int o = 8; o; o >>= 1)
                p += __shfl_xor_sync(hmask, p, o, 16);
            float s = p + g_eterm[j] + bias;
            s = (s >= 0.0f) ? s : 0.2f * s;
            mloc = fmaxf(mloc, s);
        }
        #pragma unroll
        for (int o = 16; o; o >>= 1)
            mloc = fmaxf(mloc, __shfl_xor_sync(0xffffffffu, mloc, o));
        float dloc = 0.0f;
        for (int t2 = half; t2 < deg; t2 += 2) {
            int j = beg + t2;
            int dst = g_dstS[j];
            float4 z = ((const float4*)(g_Z + (size_t)dst * DIM))[hl];
            float p = z.x * x.x + z.y * x.y + z.z * x.z + z.w * x.w;
            #pragma unroll
            for (int o = 8; o; o >>= 1)
                p += __shfl_xor_sync(hmask, p, o, 16);
            float s = p + g_eterm[j] + bias;
            s = (s >= 0.0f) ? s : 0.2f * s;
            dloc += __expf(s - mloc);
        }
        #pragma unroll
        for (int o = 16; o; o >>= 1)
            dloc += __shfl_xor_sync(0xffffffffu, dloc, o);
        float den = dloc * 0.0625f;         // /16 (each edge counted by 16 lanes)
        float inv = cscale / (den + SOFTEPS);
        for (int t2 = half; t2 < deg; t2 += 2) {
            int j = beg + t2;
            int dst = g_dstS[j];
            float4 z = ((const float4*)(g_Z + (size_t)dst * DIM))[hl];
            float p = z.x * x.x + z.y * x.y + z.z * x.z + z.w * x.w;
            #pragma unroll
            for (int o = 8; o; o >>= 1)
                p += __shfl_xor_sync(hmask, p, o, 16);
            float s = p + g_eterm[j] + bias;
            s = (s >= 0.0f) ? s : 0.2f * s;
            float al = __expf(s - mloc) * inv;  // uniform across the half
            atomicAdd(((float4*)(target + (size_t)dst * DIM)) + hl,
                      make_float4(al * x.x, al * x.y, al * x.z, al * x.w));
        }
    }
}

extern "C" void kernel_launch(void* const* d_in, const int* in_sizes, int n_in,
                              void* d_out, int out_size) {
    const int*   ei    = (const int*)d_in[0];
    const float* ea    = (const float*)d_in[1];
    const float* emb   = (const float*)d_in[2];
    const float* W     = (const float*)d_in[3];
    const float* bias  = (const float*)d_in[4];
    const float* scale = (const float*)d_in[5];

    int E  = in_sizes[1];
    int ND = in_sizes[2];
    int N  = ND / DIM;

    const int T = 256;
    int blk_n   = (N + T - 1) / T;
    int blk_e   = (E + T - 1) / T;
    int blk_n32 = (N * 32 + T - 1) / T;       // warp per node

    // ---- build src-CSR (edge_index constant per launch) ----
    k_hist<<<blk_e, T>>>(ei, E);
    k_scan1<<<blk_n, 256>>>(N);
    k_scan2<<<1, 1024>>>(blk_n);
    k_scan3<<<blk_n, T>>>(N, E);
    k_build_scatter<<<blk_e, T>>>(ei, ea, scale, E);

    float* out = (float*)d_out;
    float* out2 = out;
    float* out_copy = nullptr;
    if (out_size >= 2 * ND) {
        out_copy = out;        // mirrored inside gemm layer 0
        out2 = out + ND;
    }

    // Layer schedule: cur: emb -> A -> B; scatter target: A, B, out2.
    const int curSel[3] = {0, 1, 2};
    for (int l = 0; l < 3; l++) {
        k_gemm64<<<(N + 31) / 32, T>>>(curSel[l], emb,
                                       W + (size_t)l * DIM * DIM, out2,
                                       out_copy, N, l);
        k_fused<<<blk_n32, T>>>(curSel[l], emb, bias,
                                (l == 2) ? out2 : nullptr,
                                (l == 2) ? 0.25f : 1.0f, N, l);
    }
}